// round 10
// baseline (speedup 1.0000x reference)
#include <cuda_runtime.h>
#include <cuda_bf16.h>

// TTTConv: causal depthwise conv1d (fused conv_output + conv_states)
//   x: (B,N,D) fp32, w: (D,K), bias: (D,);  B=4, N=4096, D=2048, K=4
// d_out = [ conv_output (B,N,D) | conv_states (B,D,K) ]
// This version uses 256-bit (v8.f32) global loads/stores: each thread owns
// 8 consecutive channels, warp covers 1KB contiguous per instruction.

#define Bc 4
#define Nc 4096
#define Dc 2048
#define Kc 4
#define NT 32          // time steps per thread
#define CH 2           // chunk: 2 x 1KB-per-warp loads in flight
#define DV8 (Dc / 8)   // 8-float groups along D = 256

struct F8 { float v[8]; };

__device__ __forceinline__ F8 ldg256(const float* p) {
    F8 r;
    asm volatile("ld.global.nc.v8.f32 {%0,%1,%2,%3,%4,%5,%6,%7}, [%8];"
        : "=f"(r.v[0]), "=f"(r.v[1]), "=f"(r.v[2]), "=f"(r.v[3]),
          "=f"(r.v[4]), "=f"(r.v[5]), "=f"(r.v[6]), "=f"(r.v[7])
        : "l"(p));
    return r;
}

__device__ __forceinline__ void stg256(float* p, const F8& r) {
    asm volatile("st.global.v8.f32 [%0], {%1,%2,%3,%4,%5,%6,%7,%8};"
        :: "l"(p),
           "f"(r.v[0]), "f"(r.v[1]), "f"(r.v[2]), "f"(r.v[3]),
           "f"(r.v[4]), "f"(r.v[5]), "f"(r.v[6]), "f"(r.v[7])
        : "memory");
}

__global__ void __launch_bounds__(128, 5) ttt_conv_fused(
    const float* __restrict__ x,
    const float* __restrict__ w,
    const float* __restrict__ bias,
    float* __restrict__ out,
    float* __restrict__ states)
{
    int tid  = blockIdx.x * blockDim.x + threadIdx.x;
    int dv8  = tid % DV8;                 // 8-float group along D
    int nt   = (tid / DV8) % (Nc / NT);   // time tile
    int b    = tid / (DV8 * (Nc / NT));   // batch
    int d    = dv8 * 8;
    int n0   = nt * NT;

    // Weights: 8 channels x 4 taps; bias: 8
    float4 wv[8];
#pragma unroll
    for (int j = 0; j < 8; ++j)
        wv[j] = ((const float4*)w)[d + j];
    F8 bv = ldg256(bias + d);

    const float* xp = x   + (size_t)b * Nc * Dc + (size_t)n0 * Dc + d;
    float*       op = out + (size_t)b * Nc * Dc + (size_t)n0 * Dc + d;

    // Sliding window: x at n-3, n-2, n-1
    F8 xm3, xm2, xm1;
    if (n0 == 0) {
#pragma unroll
        for (int j = 0; j < 8; ++j) { xm3.v[j] = 0.f; xm2.v[j] = 0.f; xm1.v[j] = 0.f; }
    } else {
        xm3 = ldg256(xp - 3 * Dc);
        xm2 = ldg256(xp - 2 * Dc);
        xm1 = ldg256(xp - 1 * Dc);
    }

    for (int c = 0; c < NT / CH; ++c) {
        // ---- batch loads: CH independent 256-bit loads ----
        F8 buf[CH];
#pragma unroll
        for (int i = 0; i < CH; ++i)
            buf[i] = ldg256(xp + i * Dc);

        // ---- compute + store ----
#pragma unroll
        for (int i = 0; i < CH; ++i) {
            F8 xc = buf[i];
            F8 r;
#pragma unroll
            for (int j = 0; j < 8; ++j)
                r.v[j] = fmaf(xm3.v[j], wv[j].x,
                         fmaf(xm2.v[j], wv[j].y,
                         fmaf(xm1.v[j], wv[j].z,
                         fmaf(xc.v[j],  wv[j].w, bv.v[j]))));
            stg256(op + i * Dc, r);
            xm3 = xm2; xm2 = xm1; xm1 = xc;
        }
        xp += CH * Dc;
        op += CH * Dc;
    }

    // Last time-tile threads emit conv_states (B, D, K): k contiguous ->
    // one float4 per channel (8 per thread). Reload x[N-4] (L2 hit).
    if (n0 == Nc - NT) {
        F8 a = ldg256(xp - 4 * Dc);
        float4* sb = (float4*)states + (size_t)b * Dc + d;
#pragma unroll
        for (int j = 0; j < 8; ++j)
            sb[j] = make_float4(a.v[j], xm3.v[j], xm2.v[j], xm1.v[j]);
    }
}

extern "C" void kernel_launch(void* const* d_in, const int* in_sizes, int n_in,
                              void* d_out, int out_size)
{
    const float* x    = (const float*)d_in[0];
    const float* w    = (const float*)d_in[1];
    const float* bias = (const float*)d_in[2];
    float* out    = (float*)d_out;
    float* states = out + (size_t)Bc * Nc * Dc;

    // Bc * (Nc/NT) * DV8 threads = 4 * 128 * 256 = 131072 -> 1024 blocks of 128
    int total = Bc * (Nc / NT) * DV8;
    ttt_conv_fused<<<total / 128, 128>>>(x, w, bias, out, states);
}

// round 12
// speedup vs baseline: 1.1336x; 1.1336x over previous
#include <cuda_runtime.h>
#include <cuda_bf16.h>

// TTTConv: causal depthwise conv1d (fused conv_output + conv_states)
//   x: (B,N,D) fp32, w: (D,K), bias: (D,);  B=4, N=4096, D=2048, K=4
// d_out = [ conv_output (B,N,D) | conv_states (B,D,K) ]
//
// Final configuration (plateau-locked): per-thread sliding window along N
// over 4 consecutive channels (float4), CH=4 front-batched LDG.128 per chunk,
// 4 CTAs/SM (regs=64). Measured: ~6.65 TB/s effective DRAM (~83% of spec),
// invariant across occupancy/MLP/store-order/width variants R4-R10.

#define Bc 4
#define Nc 4096
#define Dc 2048
#define Kc 4
#define NT 32          // time steps per thread
#define CH 4           // chunk: loads batched 4-deep for MLP
#define DV (Dc / 4)    // float4 groups along D = 512

__global__ void __launch_bounds__(256, 4) ttt_conv_fused(
    const float* __restrict__ x,
    const float* __restrict__ w,
    const float* __restrict__ bias,
    float* __restrict__ out,
    float* __restrict__ states)
{
    int tid  = blockIdx.x * blockDim.x + threadIdx.x;
    int dvec = tid % DV;                 // float4 group along D
    int nt   = (tid / DV) % (Nc / NT);   // time tile
    int b    = tid / (DV * (Nc / NT));   // batch
    int d    = dvec * 4;
    int n0   = nt * NT;

    float4 wv0 = ((const float4*)w)[d + 0];
    float4 wv1 = ((const float4*)w)[d + 1];
    float4 wv2 = ((const float4*)w)[d + 2];
    float4 wv3 = ((const float4*)w)[d + 3];
    float4 bv  = ((const float4*)bias)[dvec];

    // 32-bit byte offsets (tensors << 4GB): base points at (b, n0, d)
    unsigned base = ((unsigned)b * Nc * Dc + (unsigned)n0 * Dc + (unsigned)d) * 4u;
    const char* xp = (const char*)x   + base;
    char*       op = (char*)      out + base;
    const unsigned ROW = Dc * 4u;  // byte stride per time step

    // Sliding window: x at n-3, n-2, n-1
    float4 xm3, xm2, xm1;
    if (n0 == 0) {
        xm3 = make_float4(0.f, 0.f, 0.f, 0.f);
        xm2 = xm3;
        xm1 = xm3;
    } else {
        xm3 = *(const float4*)(xp - 3 * ROW);
        xm2 = *(const float4*)(xp - 2 * ROW);
        xm1 = *(const float4*)(xp - 1 * ROW);
    }

#pragma unroll
    for (int c = 0; c < NT / CH; ++c) {
        // ---- batch loads: CH independent LDG.128 front-to-front ----
        float4 buf[CH];
#pragma unroll
        for (int i = 0; i < CH; ++i)
            buf[i] = *(const float4*)(xp + (unsigned)(c * CH + i) * ROW);

        // ---- compute + store inline (stores are fire-and-forget) ----
#pragma unroll
        for (int i = 0; i < CH; ++i) {
            float4 xc = buf[i];
            float4 r;
            r.x = fmaf(xm3.x, wv0.x, fmaf(xm2.x, wv0.y, fmaf(xm1.x, wv0.z, fmaf(xc.x, wv0.w, bv.x))));
            r.y = fmaf(xm3.y, wv1.x, fmaf(xm2.y, wv1.y, fmaf(xm1.y, wv1.z, fmaf(xc.y, wv1.w, bv.y))));
            r.z = fmaf(xm3.z, wv2.x, fmaf(xm2.z, wv2.y, fmaf(xm1.z, wv2.z, fmaf(xc.z, wv2.w, bv.z))));
            r.w = fmaf(xm3.w, wv3.x, fmaf(xm2.w, wv3.y, fmaf(xm1.w, wv3.z, fmaf(xc.w, wv3.w, bv.w))));
            *(float4*)(op + (unsigned)(c * CH + i) * ROW) = r;
            xm3 = xm2; xm2 = xm1; xm1 = xc;
        }
    }

    // Last time-tile threads emit conv_states (B, D, K): k contiguous ->
    // one float4 per channel. Window regs hold x[N-3..N-1]; reload x[N-4]
    // (L2 hit — just streamed by this thread).
    if (n0 == Nc - NT) {
        float4 a = *(const float4*)(xp + (unsigned)(NT - 4) * ROW);
        float4* sb = (float4*)states + (size_t)b * Dc + d;
        sb[0] = make_float4(a.x, xm3.x, xm2.x, xm1.x);
        sb[1] = make_float4(a.y, xm3.y, xm2.y, xm1.y);
        sb[2] = make_float4(a.z, xm3.z, xm2.z, xm1.z);
        sb[3] = make_float4(a.w, xm3.w, xm2.w, xm1.w);
    }
}

extern "C" void kernel_launch(void* const* d_in, const int* in_sizes, int n_in,
                              void* d_out, int out_size)
{
    const float* x    = (const float*)d_in[0];
    const float* w    = (const float*)d_in[1];
    const float* bias = (const float*)d_in[2];
    float* out    = (float*)d_out;
    float* states = out + (size_t)Bc * Nc * Dc;

    int total = Bc * (Nc / NT) * DV;   // 262144 threads -> 1024 blocks
    ttt_conv_fused<<<total / 256, 256>>>(x, w, bias, out, states);
}